// round 7
// baseline (speedup 1.0000x reference)
#include <cuda_runtime.h>
#include <cstdint>

#define T_ 256
#define B_ 64
#define M_ 512
#define N_ 1024
#define NB_REC 128
#define NBD 64          // blocks per direction (barrier arrivals)

// Scratch: G[dir*3+gate][t][b][n]  (gate order f,i,c)
__device__ float g_G[(size_t)6 * T_ * N_ * B_];
// h double buffer, k-pair-permuted + tf32-rounded: [buf][dir][b][kslot 1024]
__device__ float g_hP[2][2][B_ * N_];
// U packed in mma-fragment order as tf32 bit patterns:
// [dir][tile 64][chunk 8][kq 8][ks 2][gate 4][lane 32] uint4
__device__ uint4 g_Upk[1u << 21];
// per-step per-dir grid barrier counters (zeroed by k_init every launch)
__device__ unsigned g_bar[2 * T_];

struct PW { const float* p[6]; };
struct PU { const float* U[8]; const float* bia[8]; };

__device__ __forceinline__ uint32_t f2tf(float v) {
  uint32_t u; asm("cvt.rna.tf32.f32 %0, %1;" : "=r"(u) : "f"(v)); return u;
}
__device__ __forceinline__ void mma8(float* c, uint32_t a0, uint32_t a1,
                                     uint32_t a2, uint32_t a3,
                                     uint32_t b0, uint32_t b1) {
  asm volatile(
    "mma.sync.aligned.m16n8k8.row.col.f32.tf32.tf32.f32 "
    "{%0,%1,%2,%3},{%4,%5,%6,%7},{%8,%9},{%0,%1,%2,%3};\n"
    : "+f"(c[0]), "+f"(c[1]), "+f"(c[2]), "+f"(c[3])
    : "r"(a0), "r"(a1), "r"(a2), "r"(a3), "r"(b0), "r"(b1));
}
__device__ __forceinline__ void cpa16(uint32_t d, const void* s) {
  asm volatile("cp.async.cg.shared.global [%0], [%1], 16;" :: "r"(d), "l"(s));
}
__device__ __forceinline__ int kperm(int n) {        // pair (k, k+4) adjacent
  return (n & ~7) + ((n & 3) << 1) + ((n >> 2) & 1);
}

__global__ void k_init(const float* __restrict__ hidden) {
  int i = blockIdx.x * blockDim.x + threadIdx.x;   // 65536 threads
  if (i < B_ * N_) {
    int b = i >> 10, n = i & 1023;
    float v = __uint_as_float(f2tf(hidden[i]));
    g_hP[0][0][b * N_ + kperm(n)] = v;
    g_hP[0][1][b * N_ + kperm(n)] = v;
  }
  if (i < 2 * T_) g_bar[i] = 0;
}

// Pack U into fragment order (one uint4 per thread).
__global__ void __launch_bounds__(256) k_pack(PU pu) {
  unsigned i = blockIdx.x * 256 + threadIdx.x;
  unsigned lane = i & 31, g = (i >> 5) & 3, ks = (i >> 7) & 1,
           kq = (i >> 8) & 7, c = (i >> 11) & 7, tile = (i >> 14) & 63,
           dir = (i >> 20) & 1;
  int g4 = lane >> 2, tq = lane & 3;
  int row = tile * 16 + g4;
  int k = c * 128 + kq * 16 + ks * 8 + tq;
  const float* U = pu.U[dir * 4 + g];
  uint4 o;
  o.x = f2tf(U[(size_t)row * N_ + k]);
  o.y = f2tf(U[(size_t)(row + 8) * N_ + k]);
  o.z = f2tf(U[(size_t)row * N_ + k + 4]);
  o.w = f2tf(U[(size_t)(row + 8) * N_ + k + 4]);
  g_Upk[i] = o;
}

// ---------------- Phase 1: G[dg][t][b][n] = sum_m x[t_src,b,m] * W[m,n] ----
__device__ __forceinline__ float4 cvt4(float4 v) {
  float4 r;
  r.x = __uint_as_float(f2tf(v.x)); r.y = __uint_as_float(f2tf(v.y));
  r.z = __uint_as_float(f2tf(v.z)); r.w = __uint_as_float(f2tf(v.w));
  return r;
}

__global__ void __launch_bounds__(256) k_gemm_xw(const float* __restrict__ x, PW pw) {
  __shared__ __align__(16) float As[64][36];
  __shared__ __align__(16) float Bs[32][136];
  int tid = threadIdx.x;
  int wid = tid >> 5, lane = tid & 31;
  int g4 = lane >> 2, tq = lane & 3;
  int wm = wid & 1, wn = wid >> 1;
  int n0 = blockIdx.x * 128;
  int t = blockIdx.y;
  int dg = blockIdx.z;
  int dir = dg / 3;
  int t_src = dir ? (T_ - 1 - t) : t;
  const float* W = pw.p[dg];
  const float* xt = x + (size_t)t_src * (B_ * M_);

  float acc[2][4][4];
  #pragma unroll
  for (int a = 0; a < 2; a++)
    #pragma unroll
    for (int b = 0; b < 4; b++)
      #pragma unroll
      for (int cc = 0; cc < 4; cc++) acc[a][b][cc] = 0.f;

  for (int k0 = 0; k0 < M_; k0 += 32) {
    #pragma unroll
    for (int j = 0; j < 2; j++) {
      int i = tid + j * 256;
      int bb = i >> 3, kq = (i & 7) << 2;
      *(float4*)&As[bb][kq] = cvt4(*(const float4*)(xt + bb * M_ + k0 + kq));
    }
    #pragma unroll
    for (int j = 0; j < 4; j++) {
      int i = tid + j * 256;
      int kk = i >> 5, nq = (i & 31) << 2;
      *(float4*)&Bs[kk][nq] = cvt4(*(const float4*)(W + (size_t)(k0 + kk) * N_ + n0 + nq));
    }
    __syncthreads();
    #pragma unroll
    for (int ks = 0; ks < 32; ks += 8) {
      uint32_t af[2][4];
      #pragma unroll
      for (int mt = 0; mt < 2; mt++) {
        int r = wm * 32 + mt * 16 + g4;
        af[mt][0] = __float_as_uint(As[r][ks + tq]);
        af[mt][1] = __float_as_uint(As[r + 8][ks + tq]);
        af[mt][2] = __float_as_uint(As[r][ks + tq + 4]);
        af[mt][3] = __float_as_uint(As[r + 8][ks + tq + 4]);
      }
      #pragma unroll
      for (int nt = 0; nt < 4; nt++) {
        int ccol = wn * 32 + nt * 8 + g4;
        uint32_t b0 = __float_as_uint(Bs[ks + tq][ccol]);
        uint32_t b1 = __float_as_uint(Bs[ks + tq + 4][ccol]);
        #pragma unroll
        for (int mt = 0; mt < 2; mt++)
          mma8(acc[mt][nt], af[mt][0], af[mt][1], af[mt][2], af[mt][3], b0, b1);
      }
    }
    __syncthreads();
  }
  size_t gb = (size_t)(dg * T_ + t) * (N_ * B_);
  #pragma unroll
  for (int mt = 0; mt < 2; mt++) {
    int brow = wm * 32 + mt * 16 + g4;
    #pragma unroll
    for (int nt = 0; nt < 4; nt++) {
      int nc = n0 + wn * 32 + nt * 8 + 2 * tq;
      *(float2*)&g_G[gb + (size_t)brow * N_ + nc] =
          make_float2(acc[mt][nt][0], acc[mt][nt][1]);
      *(float2*)&g_G[gb + (size_t)(brow + 8) * N_ + nc] =
          make_float2(acc[mt][nt][2], acc[mt][nt][3]);
    }
  }
}

// ---------------- Phase 2: persistent recurrent kernel ---------------------
// 512 thr. Warp (rg, kq): rows rg*32..+32 (gates 2rg,2rg+1), 64 b-cols,
// k slice kq*16 per 128-k chunk. 8 chunks; h via 4-stage cp.async pipeline;
// U register double-buffered (4 uint4 per chunk per warp).
#define HSTR 136                   // floats per b-row (128 used + 8 pad)
#define HSTAGE 8704                // 64 * 136 words per stage
#define ZSOFF 34816                // 4 * HSTAGE
#define ZS(q, r, cl) (ZSOFF + (((q) * 64 + (r)) * 66 + (cl)))
#define SMEM_WORDS (ZSOFF + 4 * 64 * 66)   // 51712 words = 206848 B

__global__ void __launch_bounds__(512) k_recur(PU pu, float* __restrict__ out) {
  extern __shared__ float sm[];
  uint32_t smb = (uint32_t)__cvta_generic_to_shared(sm);
  int tid = threadIdx.x, wid = tid >> 5, lane = tid & 31;
  int g4 = lane >> 2, tq = lane & 3;
  int dir = blockIdx.x >> 6, tile = blockIdx.x & 63, rn = tile << 4;
  int rg = wid & 1, kq = wid >> 1;

  const uint4* upk = g_Upk + (((size_t)dir * 64 + tile) << 14);
  // uint4 index for (c, ks, gate=2rg): (((c*8+kq)*2+ks)*4 + 2*rg)*32 + lane
  int ub_kq = ((kq * 2) * 4 + 2 * rg) * 32 + lane;   // c=0, ks=0 base

  // staging: 4 cp.async per thread per chunk
  int stg_b = 0, stg_g;
  { int unit = tid; stg_b = unit >> 5; stg_g = (unit & 31) << 2; }

  // elementwise ownership: b = tid>>3, n = rn + nn, nn+1
  int b_e = tid >> 3;
  int nn = (tid & 7) << 1;

  float bia[4][2];
  #pragma unroll
  for (int g = 0; g < 4; g++) {
    bia[g][0] = pu.bia[dir * 4 + g][rn + nn];
    bia[g][1] = pu.bia[dir * 4 + g][rn + nn + 1];
  }
  const float* Gb0 = g_G + (size_t)(dir * 3 + 0) * T_ * N_ * B_;
  const float* Gb1 = g_G + (size_t)(dir * 3 + 1) * T_ * N_ * B_;
  const float* Gb2 = g_G + (size_t)(dir * 3 + 2) * T_ * N_ * B_;
  int hslot0 = kperm(rn + nn), hslot1 = kperm(rn + nn + 1);
  unsigned* barp = &g_bar[dir * T_];

  float creg[2] = {0.f, 0.f};

  for (int s = 0; s < T_; ++s) {
    const float* hsrc = g_hP[s & 1][dir];

    // issue h chunks 0..2 into stages 0..2
    #pragma unroll
    for (int c0 = 0; c0 < 3; c0++) {
      #pragma unroll
      for (int j = 0; j < 4; j++) {
        int unit = tid + j * 512;
        int b = unit >> 5, g16 = (unit & 31) << 2;
        cpa16(smb + ((c0 & 3) * HSTAGE + b * HSTR + g16) * 4,
              hsrc + b * N_ + c0 * 128 + g16);
      }
      asm volatile("cp.async.commit_group;");
    }

    // prefetch this step's G (coalesced float2, [t][b][n] layout)
    size_t goff = ((size_t)s * B_ + b_e) * N_ + rn + nn;
    float2 gq0 = __ldg((const float2*)(Gb0 + goff));
    float2 gq1 = __ldg((const float2*)(Gb1 + goff));
    float2 gq2 = __ldg((const float2*)(Gb2 + goff));

    // U for chunk 0
    uint4 Uc[4], Un[4];
    Uc[0] = __ldg(upk + ub_kq);
    Uc[1] = __ldg(upk + ub_kq + 32);
    Uc[2] = __ldg(upk + ub_kq + 128);
    Uc[3] = __ldg(upk + ub_kq + 160);

    float acc[2][8][4];
    #pragma unroll
    for (int m = 0; m < 2; m++)
      #pragma unroll
      for (int nt = 0; nt < 8; nt++)
        #pragma unroll
        for (int cc = 0; cc < 4; cc++) acc[m][nt][cc] = 0.f;

    #pragma unroll 1
    for (int c = 0; c < 8; ++c) {
      if (c < 6)      asm volatile("cp.async.wait_group 2;");
      else if (c == 6) asm volatile("cp.async.wait_group 1;");
      else            asm volatile("cp.async.wait_group 0;");
      __syncthreads();

      if (c < 5) {   // stage (c+3)&3 held chunk c-1: all warps past it
        int cn = c + 3;
        #pragma unroll
        for (int j = 0; j < 4; j++) {
          int unit = tid + j * 512;
          int b = unit >> 5, g16 = (unit & 31) << 2;
          cpa16(smb + ((cn & 3) * HSTAGE + b * HSTR + g16) * 4,
                hsrc + b * N_ + cn * 128 + g16);
        }
        asm volatile("cp.async.commit_group;");
      }

      // prefetch next chunk's U (step-invariant addresses; (c+1)&7 wraps)
      int cnx = (c + 1) & 7;
      int ub = ub_kq + cnx * 2048;   // c stride = 8kq*2ks*4g*32 = 2048 uint4
      Un[0] = __ldg(upk + ub);
      Un[1] = __ldg(upk + ub + 32);
      Un[2] = __ldg(upk + ub + 128);
      Un[3] = __ldg(upk + ub + 160);

      const float* bb = sm + (c & 3) * HSTAGE + kq * 16 + 2 * tq;
      #pragma unroll
      for (int ks = 0; ks < 2; ++ks) {
        uint4 A0 = Uc[ks * 2], A1 = Uc[ks * 2 + 1];
        #pragma unroll
        for (int nt = 0; nt < 8; ++nt) {
          uint2 Bv = *(const uint2*)(bb + ks * 8 + (nt * 8 + g4) * HSTR);
          mma8(acc[0][nt], A0.x, A0.y, A0.z, A0.w, Bv.x, Bv.y);
          mma8(acc[1][nt], A1.x, A1.y, A1.z, A1.w, Bv.x, Bv.y);
        }
      }
      Uc[0] = Un[0]; Uc[1] = Un[1]; Uc[2] = Un[2]; Uc[3] = Un[3];
    }

    // z reduction: phase A (kq<4 write), phase B (kq>=4 add)
    if (kq < 4) {
      #pragma unroll
      for (int m = 0; m < 2; m++) {
        int gate = 2 * rg + m;
        #pragma unroll
        for (int nt = 0; nt < 8; nt++) {
          int cl = nt * 8 + 2 * tq;
          *(float2*)&sm[ZS(kq, gate * 16 + g4, cl)] =
              make_float2(acc[m][nt][0], acc[m][nt][1]);
          *(float2*)&sm[ZS(kq, gate * 16 + g4 + 8, cl)] =
              make_float2(acc[m][nt][2], acc[m][nt][3]);
        }
      }
    }
    __syncthreads();
    if (kq >= 4) {
      int q = kq - 4;
      #pragma unroll
      for (int m = 0; m < 2; m++) {
        int gate = 2 * rg + m;
        #pragma unroll
        for (int nt = 0; nt < 8; nt++) {
          int cl = nt * 8 + 2 * tq;
          float2* p0 = (float2*)&sm[ZS(q, gate * 16 + g4, cl)];
          float2 v0 = *p0; v0.x += acc[m][nt][0]; v0.y += acc[m][nt][1]; *p0 = v0;
          float2* p1 = (float2*)&sm[ZS(q, gate * 16 + g4 + 8, cl)];
          float2 v1 = *p1; v1.x += acc[m][nt][2]; v1.y += acc[m][nt][3]; *p1 = v1;
        }
      }
    }
    __syncthreads();

    // elementwise LSTM cell (2 consecutive n per thread, one b)
    float z[4][2];
    #pragma unroll
    for (int g = 0; g < 4; g++) {
      #pragma unroll
      for (int e = 0; e < 2; e++) {
        float zz = bia[g][e];
        #pragma unroll
        for (int q = 0; q < 4; q++) zz += sm[ZS(q, g * 16 + nn + e, b_e)];
        z[g][e] = zz;
      }
    }
    float* hdst = g_hP[(s + 1) & 1][dir];
    int t_out = dir ? (T_ - 1 - s) : s;
    float2 ho;
    #pragma unroll
    for (int e = 0; e < 2; e++) {
      float gf = e ? gq0.y : gq0.x;
      float gi = e ? gq1.y : gq1.x;
      float gc = e ? gq2.y : gq2.x;
      float zf = z[0][e] + gf, zi = z[1][e] + gi;
      float zc = z[2][e] + gc, zo = z[3][e] + gf;   // o reuses gf (ref bug)
      float f  = 1.f / (1.f + __expf(-zf));
      float ig = 1.f / (1.f + __expf(-zi));
      float o  = 1.f / (1.f + __expf(-zo));
      float cn = f * creg[e] + ig * tanhf(zc);
      creg[e] = cn;
      float h = o * tanhf(cn);
      ((float*)&ho)[e] = h;
      __stcg(hdst + b_e * N_ + (e ? hslot1 : hslot0), __uint_as_float(f2tf(h)));
    }
    *(float2*)(out + ((size_t)t_out * B_ + b_e) * (2 * N_) +
               (size_t)dir * N_ + rn + nn) = ho;

    // per-direction grid barrier (per-step counter, replay-safe)
    if (s < T_ - 1) {
      __threadfence();
      __syncthreads();
      if (tid == 0) {
        unsigned v = atomicAdd(&barp[s], 1) + 1;
        if (v < NBD) {
          while (*(volatile unsigned*)&barp[s] < NBD) { __nanosleep(32); }
        }
      }
      __syncthreads();
    }
  }
}

extern "C" void kernel_launch(void* const* d_in, const int* in_sizes, int n_in,
                              void* d_out, int out_size) {
  const float* x      = (const float*)d_in[0];
  const float* hidden = (const float*)d_in[1];
  PW pw;
  pw.p[0] = (const float*)d_in[2];   // Wf1
  pw.p[1] = (const float*)d_in[3];   // Wi1
  pw.p[2] = (const float*)d_in[4];   // Wc1
  pw.p[3] = (const float*)d_in[13];  // Wf2
  pw.p[4] = (const float*)d_in[14];  // Wi2
  pw.p[5] = (const float*)d_in[15];  // Wc2

  PU pu;  // gate order f,i,c,o
  pu.U[0] = (const float*)d_in[5];   // Uf1
  pu.U[1] = (const float*)d_in[6];   // Ui1
  pu.U[2] = (const float*)d_in[8];   // Uc1
  pu.U[3] = (const float*)d_in[7];   // Uo1
  pu.U[4] = (const float*)d_in[16];  // Uf2
  pu.U[5] = (const float*)d_in[17];  // Ui2
  pu.U[6] = (const float*)d_in[19];  // Uc2
  pu.U[7] = (const float*)d_in[18];  // Uo2
  pu.bia[0] = (const float*)d_in[9];   // bf1
  pu.bia[1] = (const float*)d_in[10];  // bi1
  pu.bia[2] = (const float*)d_in[12];  // bc1
  pu.bia[3] = (const float*)d_in[11];  // bo1
  pu.bia[4] = (const float*)d_in[20];  // bf2
  pu.bia[5] = (const float*)d_in[21];  // bi2
  pu.bia[6] = (const float*)d_in[23];  // bc2
  pu.bia[7] = (const float*)d_in[22];  // bo2

  static int smem_set = 0;
  if (!smem_set) {
    cudaFuncSetAttribute(k_recur, cudaFuncAttributeMaxDynamicSharedMemorySize,
                         SMEM_WORDS * (int)sizeof(float));
    smem_set = 1;
  }

  k_init<<<256, 256>>>(hidden);
  k_pack<<<8192, 256>>>(pu);
  k_gemm_xw<<<dim3(8, 256, 6), 256>>>(x, pw);
  k_recur<<<NB_REC, 512, SMEM_WORDS * sizeof(float)>>>(pu, (float*)d_out);
}

// round 8
// speedup vs baseline: 1.2156x; 1.2156x over previous
#include <cuda_runtime.h>
#include <cstdint>

#define T_ 256
#define B_ 64
#define M_ 512
#define N_ 1024
#define NB_REC 128
#define NBD 64          // blocks per direction (barrier arrivals)

// Scratch: G[dir*3+gate][t][b][n]  (gate order f,i,c)
__device__ float g_G[(size_t)6 * T_ * N_ * B_];
// h double buffer, k-pair-permuted + tf32-rounded: [buf][dir][b][kslot 1024]
__device__ float g_hP[2][2][B_ * N_];
// U packed in mma-fragment order as tf32 bit patterns:
// [dir][tile 64][kq 8][c 4][ks 4][gate 4][lane 32] uint4
__device__ uint4 g_Upk[1u << 21];
// per-step per-dir grid barrier counters (zeroed by k_init every launch)
__device__ unsigned g_bar[2 * T_];

struct PW { const float* p[6]; };
struct PU { const float* U[8]; const float* bia[8]; };

__device__ __forceinline__ uint32_t f2tf(float v) {
  uint32_t u; asm("cvt.rna.tf32.f32 %0, %1;" : "=r"(u) : "f"(v)); return u;
}
__device__ __forceinline__ void mma8(float* c, uint32_t a0, uint32_t a1,
                                     uint32_t a2, uint32_t a3,
                                     uint32_t b0, uint32_t b1) {
  asm volatile(
    "mma.sync.aligned.m16n8k8.row.col.f32.tf32.tf32.f32 "
    "{%0,%1,%2,%3},{%4,%5,%6,%7},{%8,%9},{%0,%1,%2,%3};\n"
    : "+f"(c[0]), "+f"(c[1]), "+f"(c[2]), "+f"(c[3])
    : "r"(a0), "r"(a1), "r"(a2), "r"(a3), "r"(b0), "r"(b1));
}
__device__ __forceinline__ void cpa16(uint32_t d, const void* s) {
  asm volatile("cp.async.cg.shared.global [%0], [%1], 16;" :: "r"(d), "l"(s));
}
__device__ __forceinline__ void barp64(int id) {
  asm volatile("bar.sync %0, 64;" :: "r"(id) : "memory");
}
__device__ __forceinline__ int kperm(int n) {        // pair (k, k+4) adjacent
  return (n & ~7) + ((n & 3) << 1) + ((n >> 2) & 1);
}
__device__ __forceinline__ float sigm_f(float x) {
  return __fdividef(1.f, 1.f + __expf(-x));
}
__device__ __forceinline__ float tanh_f(float x) {
  return 1.f - __fdividef(2.f, __expf(2.f * x) + 1.f);
}

__global__ void k_init(const float* __restrict__ hidden) {
  int i = blockIdx.x * blockDim.x + threadIdx.x;   // 65536 threads
  if (i < B_ * N_) {
    int b = i >> 10, n = i & 1023;
    float v = __uint_as_float(f2tf(hidden[i]));
    g_hP[0][0][b * N_ + kperm(n)] = v;
    g_hP[0][1][b * N_ + kperm(n)] = v;
  }
  if (i < 2 * T_) g_bar[i] = 0;
}

// Pack U into fragment order (one uint4 per thread).
__global__ void __launch_bounds__(256) k_pack(PU pu) {
  unsigned i = blockIdx.x * 256 + threadIdx.x;
  unsigned lane = i & 31, g = (i >> 5) & 3, ks = (i >> 7) & 3,
           c = (i >> 9) & 3, kq = (i >> 11) & 7, tile = (i >> 14) & 63,
           dir = (i >> 20) & 1;
  int g4 = lane >> 2, tq = lane & 3;
  int row = tile * 16 + g4;
  int k = kq * 128 + c * 32 + ks * 8 + tq;
  const float* U = pu.U[dir * 4 + g];
  uint4 o;
  o.x = f2tf(U[(size_t)row * N_ + k]);
  o.y = f2tf(U[(size_t)(row + 8) * N_ + k]);
  o.z = f2tf(U[(size_t)row * N_ + k + 4]);
  o.w = f2tf(U[(size_t)(row + 8) * N_ + k + 4]);
  g_Upk[i] = o;
}

// ---------------- Phase 1: G[dg][t][b][n] = sum_m x[t_src,b,m] * W[m,n] ----
__device__ __forceinline__ float4 cvt4(float4 v) {
  float4 r;
  r.x = __uint_as_float(f2tf(v.x)); r.y = __uint_as_float(f2tf(v.y));
  r.z = __uint_as_float(f2tf(v.z)); r.w = __uint_as_float(f2tf(v.w));
  return r;
}

__global__ void __launch_bounds__(256) k_gemm_xw(const float* __restrict__ x, PW pw) {
  __shared__ __align__(16) float As[64][36];
  __shared__ __align__(16) float Bs[32][136];
  int tid = threadIdx.x;
  int wid = tid >> 5, lane = tid & 31;
  int g4 = lane >> 2, tq = lane & 3;
  int wm = wid & 1, wn = wid >> 1;
  int n0 = blockIdx.x * 128;
  int t = blockIdx.y;
  int dg = blockIdx.z;
  int dir = dg / 3;
  int t_src = dir ? (T_ - 1 - t) : t;
  const float* W = pw.p[dg];
  const float* xt = x + (size_t)t_src * (B_ * M_);

  float acc[2][4][4];
  #pragma unroll
  for (int a = 0; a < 2; a++)
    #pragma unroll
    for (int b = 0; b < 4; b++)
      #pragma unroll
      for (int cc = 0; cc < 4; cc++) acc[a][b][cc] = 0.f;

  for (int k0 = 0; k0 < M_; k0 += 32) {
    #pragma unroll
    for (int j = 0; j < 2; j++) {
      int i = tid + j * 256;
      int bb = i >> 3, kq = (i & 7) << 2;
      *(float4*)&As[bb][kq] = cvt4(*(const float4*)(xt + bb * M_ + k0 + kq));
    }
    #pragma unroll
    for (int j = 0; j < 4; j++) {
      int i = tid + j * 256;
      int kk = i >> 5, nq = (i & 31) << 2;
      *(float4*)&Bs[kk][nq] = cvt4(*(const float4*)(W + (size_t)(k0 + kk) * N_ + n0 + nq));
    }
    __syncthreads();
    #pragma unroll
    for (int ks = 0; ks < 32; ks += 8) {
      uint32_t af[2][4];
      #pragma unroll
      for (int mt = 0; mt < 2; mt++) {
        int r = wm * 32 + mt * 16 + g4;
        af[mt][0] = __float_as_uint(As[r][ks + tq]);
        af[mt][1] = __float_as_uint(As[r + 8][ks + tq]);
        af[mt][2] = __float_as_uint(As[r][ks + tq + 4]);
        af[mt][3] = __float_as_uint(As[r + 8][ks + tq + 4]);
      }
      #pragma unroll
      for (int nt = 0; nt < 4; nt++) {
        int ccol = wn * 32 + nt * 8 + g4;
        uint32_t b0 = __float_as_uint(Bs[ks + tq][ccol]);
        uint32_t b1 = __float_as_uint(Bs[ks + tq + 4][ccol]);
        #pragma unroll
        for (int mt = 0; mt < 2; mt++)
          mma8(acc[mt][nt], af[mt][0], af[mt][1], af[mt][2], af[mt][3], b0, b1);
      }
    }
    __syncthreads();
  }
  size_t gb = (size_t)(dg * T_ + t) * (N_ * B_);
  #pragma unroll
  for (int mt = 0; mt < 2; mt++) {
    int brow = wm * 32 + mt * 16 + g4;
    #pragma unroll
    for (int nt = 0; nt < 4; nt++) {
      int nc = n0 + wn * 32 + nt * 8 + 2 * tq;
      *(float2*)&g_G[gb + (size_t)brow * N_ + nc] =
          make_float2(acc[mt][nt][0], acc[mt][nt][1]);
      *(float2*)&g_G[gb + (size_t)(brow + 8) * N_ + nc] =
          make_float2(acc[mt][nt][2], acc[mt][nt][3]);
    }
  }
}

// ---------------- Phase 2: persistent recurrent kernel ---------------------
// 512 thr. Warp PAIR kq (warps 2kq, 2kq+1) owns k-slice [kq*128, kq*128+128),
// staged privately in 2x(64b x 40) smem ring with named-barrier sync.
// Warp rg in pair handles gates 2rg, 2rg+1 (32 of the 64 rows).
#define BUFW 2560                  // 64 * 40 words per chunk buffer
#define PAIRW 5120                 // 2 buffers
#define SMEM_BYTES (8 * PAIRW * 4) // 163840
// zs overlaid on staging region after mainloop: [q 8][r 64][cl 66]
#define ZS(q, r, cl) (((q) * 64 + (r)) * 66 + (cl))

__global__ void __launch_bounds__(512) k_recur(PU pu, float* __restrict__ out) {
  extern __shared__ float sm[];
  uint32_t smb = (uint32_t)__cvta_generic_to_shared(sm);
  int tid = threadIdx.x, wid = tid >> 5, lane = tid & 31;
  int g4 = lane >> 2, tq = lane & 3;
  int dir = blockIdx.x >> 6, tile = blockIdx.x & 63, rn = tile << 4;
  int rg = wid & 1, kq = wid >> 1;
  int pt = rg * 32 + lane;                 // pair-local tid 0..63
  int barid = 1 + kq;

  const uint4* upk = g_Upk + (((size_t)dir * 64 + tile) << 14)
                     + kq * 2048 + 2 * rg * 32 + lane;
  // staging addressing (per pair): thread copies 8 x 16B per chunk
  int stg_b = 0, stg_s = 0;
  uint32_t pair_smb = smb + kq * PAIRW * 4;

  // elementwise ownership: b = tid>>3, n = rn + nn, nn+1
  int b_e = tid >> 3;
  int nn = (tid & 7) << 1;

  float bia[4][2];
  #pragma unroll
  for (int g = 0; g < 4; g++) {
    bia[g][0] = pu.bia[dir * 4 + g][rn + nn];
    bia[g][1] = pu.bia[dir * 4 + g][rn + nn + 1];
  }
  const float* Gb0 = g_G + (size_t)(dir * 3 + 0) * T_ * N_ * B_;
  const float* Gb1 = g_G + (size_t)(dir * 3 + 1) * T_ * N_ * B_;
  const float* Gb2 = g_G + (size_t)(dir * 3 + 2) * T_ * N_ * B_;
  int hslot0 = kperm(rn + nn), hslot1 = kperm(rn + nn + 1);
  unsigned* barp = &g_bar[dir * T_];

  float creg[2] = {0.f, 0.f};

  for (int s = 0; s < T_; ++s) {
    const float* hsrc = g_hP[s & 1][dir];
    const float* hkq = hsrc + kq * 128;

    // stage chunks 0,1 into bufs 0,1 (pair-private)
    #pragma unroll
    for (int c0 = 0; c0 < 2; c0++) {
      #pragma unroll
      for (int j = 0; j < 8; j++) {
        int unit = pt + j * 64;
        int b = unit >> 3, seg = unit & 7;
        cpa16(pair_smb + (c0 * BUFW + b * 40 + seg * 4) * 4,
              hkq + b * N_ + c0 * 32 + seg * 4);
      }
      asm volatile("cp.async.commit_group;");
    }

    // prefetch this step's G (coalesced float2, [t][b][n] layout)
    size_t goff = ((size_t)s * B_ + b_e) * N_ + rn + nn;
    float2 gq0 = __ldg((const float2*)(Gb0 + goff));
    float2 gq1 = __ldg((const float2*)(Gb1 + goff));
    float2 gq2 = __ldg((const float2*)(Gb2 + goff));

    float acc[2][8][4];
    #pragma unroll
    for (int m = 0; m < 2; m++)
      #pragma unroll
      for (int nt = 0; nt < 8; nt++)
        #pragma unroll
        for (int cc = 0; cc < 4; cc++) acc[m][nt][cc] = 0.f;

    #pragma unroll
    for (int c = 0; c < 4; ++c) {
      if (c < 3) asm volatile("cp.async.wait_group 1;");
      else       asm volatile("cp.async.wait_group 0;");
      barp64(barid);                     // chunk c visible to both warps

      const float* bb = sm + kq * PAIRW + (c & 1) * BUFW + 2 * tq;
      const uint4* up = upk + c * 512;
      #pragma unroll
      for (int ks = 0; ks < 4; ++ks) {
        uint4 A0 = __ldg(up + ks * 128);
        uint4 A1 = __ldg(up + ks * 128 + 32);
        #pragma unroll
        for (int nt = 0; nt < 8; ++nt) {
          uint2 Bv = *(const uint2*)(bb + (nt * 8 + g4) * 40 + ks * 8);
          mma8(acc[0][nt], A0.x, A0.y, A0.z, A0.w, Bv.x, Bv.y);
          mma8(acc[1][nt], A1.x, A1.y, A1.z, A1.w, Bv.x, Bv.y);
        }
      }
      if (c < 2) {
        barp64(barid);                   // both warps done with buf c&1
        int cn = c + 2;
        #pragma unroll
        for (int j = 0; j < 8; j++) {
          int unit = pt + j * 64;
          int b = unit >> 3, seg = unit & 7;
          cpa16(pair_smb + ((c & 1) * BUFW + b * 40 + seg * 4) * 4,
                hkq + b * N_ + cn * 32 + seg * 4);
        }
        asm volatile("cp.async.commit_group;");
      }
    }

    __syncthreads();                     // staging drained; reuse smem as zs

    // write k-partials: zs[kq][gate*16+n][b]
    #pragma unroll
    for (int m = 0; m < 2; m++) {
      int gate = 2 * rg + m;
      #pragma unroll
      for (int nt = 0; nt < 8; nt++) {
        int cl = nt * 8 + 2 * tq;
        *(float2*)&sm[ZS(kq, gate * 16 + g4, cl)] =
            make_float2(acc[m][nt][0], acc[m][nt][1]);
        *(float2*)&sm[ZS(kq, gate * 16 + g4 + 8, cl)] =
            make_float2(acc[m][nt][2], acc[m][nt][3]);
      }
    }
    __syncthreads();

    // elementwise LSTM cell (2 consecutive n per thread, one b)
    float z[4][2];
    #pragma unroll
    for (int g = 0; g < 4; g++) {
      #pragma unroll
      for (int e = 0; e < 2; e++) {
        float zz = bia[g][e];
        #pragma unroll
        for (int q = 0; q < 8; q++) zz += sm[ZS(q, g * 16 + nn + e, b_e)];
        z[g][e] = zz;
      }
    }
    float* hdst = g_hP[(s + 1) & 1][dir];
    int t_out = dir ? (T_ - 1 - s) : s;
    float2 ho;
    #pragma unroll
    for (int e = 0; e < 2; e++) {
      float gf = e ? gq0.y : gq0.x;
      float gi = e ? gq1.y : gq1.x;
      float gc = e ? gq2.y : gq2.x;
      float zf = z[0][e] + gf, zi = z[1][e] + gi;
      float zc = z[2][e] + gc, zo = z[3][e] + gf;   // o reuses gf (ref bug)
      float f  = sigm_f(zf);
      float ig = sigm_f(zi);
      float o  = sigm_f(zo);
      float cn = f * creg[e] + ig * tanh_f(zc);
      creg[e] = cn;
      float h = o * tanh_f(cn);
      ((float*)&ho)[e] = h;
      __stcg(hdst + b_e * N_ + (e ? hslot1 : hslot0), __uint_as_float(f2tf(h)));
    }
    *(float2*)(out + ((size_t)t_out * B_ + b_e) * (2 * N_) +
               (size_t)dir * N_ + rn + nn) = ho;

    // per-direction grid barrier (per-step counter, replay-safe)
    if (s < T_ - 1) {
      __threadfence();
      __syncthreads();
      if (tid == 0) {
        unsigned v = atomicAdd(&barp[s], 1) + 1;
        if (v < NBD) {
          while (*(volatile unsigned*)&barp[s] < NBD) { __nanosleep(32); }
        }
      }
      __syncthreads();
    }
  }
}

extern "C" void kernel_launch(void* const* d_in, const int* in_sizes, int n_in,
                              void* d_out, int out_size) {
  const float* x      = (const float*)d_in[0];
  const float* hidden = (const float*)d_in[1];
  PW pw;
  pw.p[0] = (const float*)d_in[2];   // Wf1
  pw.p[1] = (const float*)d_in[3];   // Wi1
  pw.p[2] = (const float*)d_in[4];   // Wc1
  pw.p[3] = (const float*)d_in[13];  // Wf2
  pw.p[4] = (const float*)d_in[14];  // Wi2
  pw.p[5] = (const float*)d_in[15];  // Wc2

  PU pu;  // gate order f,i,c,o
  pu.U[0] = (const float*)d_in[5];   // Uf1
  pu.U[1] = (const float*)d_in[6];   // Ui1
  pu.U[2] = (const float*)d_in[8];   // Uc1
  pu.U[3] = (const float*)d_in[7];   // Uo1
  pu.U[4] = (const float*)d_in[16];  // Uf2
  pu.U[5] = (const float*)d_in[17];  // Ui2
  pu.U[6] = (const float*)d_in[19];  // Uc2
  pu.U[7] = (const float*)d_in[18];  // Uo2
  pu.bia[0] = (const float*)d_in[9];   // bf1
  pu.bia[1] = (const float*)d_in[10];  // bi1
  pu.bia[2] = (const float*)d_in[12];  // bc1
  pu.bia[3] = (const float*)d_in[11];  // bo1
  pu.bia[4] = (const float*)d_in[20];  // bf2
  pu.bia[5] = (const float*)d_in[21];  // bi2
  pu.bia[6] = (const float*)d_in[23];  // bc2
  pu.bia[7] = (const float*)d_in[22];  // bo2

  static int smem_set = 0;
  if (!smem_set) {
    cudaFuncSetAttribute(k_recur, cudaFuncAttributeMaxDynamicSharedMemorySize,
                         SMEM_BYTES);
    smem_set = 1;
  }

  k_init<<<256, 256>>>(hidden);
  k_pack<<<8192, 256>>>(pu);
  k_gemm_xw<<<dim3(8, 256, 6), 256>>>(x, pw);
  k_recur<<<NB_REC, 512, SMEM_BYTES>>>(pu, (float*)d_out);
}

// round 9
// speedup vs baseline: 1.2165x; 1.0007x over previous
#include <cuda_runtime.h>
#include <cstdint>

#define T_ 256
#define B_ 64
#define M_ 512
#define N_ 1024
#define NB_REC 128
#define NBD 64          // blocks per direction (barrier arrivals)

// Scratch: G[dir*3+gate][t][b][n]  (gate order f,i,c)
__device__ float g_G[(size_t)6 * T_ * N_ * B_];
// h double buffer, k-pair-permuted + tf32-rounded: [buf][dir][b][kslot 1024]
__device__ float g_hP[2][2][B_ * N_];
// U packed in mma-fragment order as tf32 bit patterns:
// [dir][tile 64][kq 8][c 4][ks 4][gate 4][lane 32] uint4
__device__ uint4 g_Upk[1u << 21];
// per-step per-dir grid barrier counters (zeroed by k_init every launch)
__device__ unsigned g_bar[2 * T_];

struct PW { const float* p[6]; };
struct PU { const float* U[8]; const float* bia[8]; };

__device__ __forceinline__ uint32_t f2tf(float v) {
  uint32_t u; asm("cvt.rna.tf32.f32 %0, %1;" : "=r"(u) : "f"(v)); return u;
}
__device__ __forceinline__ void mma8(float* c, uint32_t a0, uint32_t a1,
                                     uint32_t a2, uint32_t a3,
                                     uint32_t b0, uint32_t b1) {
  asm volatile(
    "mma.sync.aligned.m16n8k8.row.col.f32.tf32.tf32.f32 "
    "{%0,%1,%2,%3},{%4,%5,%6,%7},{%8,%9},{%0,%1,%2,%3};\n"
    : "+f"(c[0]), "+f"(c[1]), "+f"(c[2]), "+f"(c[3])
    : "r"(a0), "r"(a1), "r"(a2), "r"(a3), "r"(b0), "r"(b1));
}
__device__ __forceinline__ void cpa16(uint32_t d, const void* s) {
  asm volatile("cp.async.cg.shared.global [%0], [%1], 16;" :: "r"(d), "l"(s));
}
__device__ __forceinline__ void barp64(int id) {
  asm volatile("bar.sync %0, 64;" :: "r"(id) : "memory");
}
__device__ __forceinline__ int kperm(int n) {        // pair (k, k+4) adjacent
  return (n & ~7) + ((n & 3) << 1) + ((n >> 2) & 1);
}
__device__ __forceinline__ float sigm_f(float x) {
  return __fdividef(1.f, 1.f + __expf(-x));
}
__device__ __forceinline__ float tanh_f(float x) {
  return 1.f - __fdividef(2.f, __expf(2.f * x) + 1.f);
}

__global__ void k_init(const float* __restrict__ hidden) {
  int i = blockIdx.x * blockDim.x + threadIdx.x;   // 65536 threads
  if (i < B_ * N_) {
    int b = i >> 10, n = i & 1023;
    float v = __uint_as_float(f2tf(hidden[i]));
    g_hP[0][0][b * N_ + kperm(n)] = v;
    g_hP[0][1][b * N_ + kperm(n)] = v;
  }
  if (i < 2 * T_) g_bar[i] = 0;
}

// Pack U into fragment order (one uint4 per thread).
__global__ void __launch_bounds__(256) k_pack(PU pu) {
  unsigned i = blockIdx.x * 256 + threadIdx.x;
  unsigned lane = i & 31, g = (i >> 5) & 3, ks = (i >> 7) & 3,
           c = (i >> 9) & 3, kq = (i >> 11) & 7, tile = (i >> 14) & 63,
           dir = (i >> 20) & 1;
  int g4 = lane >> 2, tq = lane & 3;
  int row = tile * 16 + g4;
  int k = kq * 128 + c * 32 + ks * 8 + tq;
  const float* U = pu.U[dir * 4 + g];
  uint4 o;
  o.x = f2tf(U[(size_t)row * N_ + k]);
  o.y = f2tf(U[(size_t)(row + 8) * N_ + k]);
  o.z = f2tf(U[(size_t)row * N_ + k + 4]);
  o.w = f2tf(U[(size_t)(row + 8) * N_ + k + 4]);
  g_Upk[i] = o;
}

// ---------------- Phase 1: G[dg][t][b][n] = sum_m x[t_src,b,m] * W[m,n] ----
__device__ __forceinline__ float4 cvt4(float4 v) {
  float4 r;
  r.x = __uint_as_float(f2tf(v.x)); r.y = __uint_as_float(f2tf(v.y));
  r.z = __uint_as_float(f2tf(v.z)); r.w = __uint_as_float(f2tf(v.w));
  return r;
}

__global__ void __launch_bounds__(256) k_gemm_xw(const float* __restrict__ x, PW pw) {
  __shared__ __align__(16) float As[64][36];
  __shared__ __align__(16) float Bs[32][136];
  int tid = threadIdx.x;
  int wid = tid >> 5, lane = tid & 31;
  int g4 = lane >> 2, tq = lane & 3;
  int wm = wid & 1, wn = wid >> 1;
  int n0 = blockIdx.x * 128;
  int t = blockIdx.y;
  int dg = blockIdx.z;
  int dir = dg / 3;
  int t_src = dir ? (T_ - 1 - t) : t;
  const float* W = pw.p[dg];
  const float* xt = x + (size_t)t_src * (B_ * M_);

  float acc[2][4][4];
  #pragma unroll
  for (int a = 0; a < 2; a++)
    #pragma unroll
    for (int b = 0; b < 4; b++)
      #pragma unroll
      for (int cc = 0; cc < 4; cc++) acc[a][b][cc] = 0.f;

  for (int k0 = 0; k0 < M_; k0 += 32) {
    #pragma unroll
    for (int j = 0; j < 2; j++) {
      int i = tid + j * 256;
      int bb = i >> 3, kq = (i & 7) << 2;
      *(float4*)&As[bb][kq] = cvt4(*(const float4*)(xt + bb * M_ + k0 + kq));
    }
    #pragma unroll
    for (int j = 0; j < 4; j++) {
      int i = tid + j * 256;
      int kk = i >> 5, nq = (i & 31) << 2;
      *(float4*)&Bs[kk][nq] = cvt4(*(const float4*)(W + (size_t)(k0 + kk) * N_ + n0 + nq));
    }
    __syncthreads();
    #pragma unroll
    for (int ks = 0; ks < 32; ks += 8) {
      uint32_t af[2][4];
      #pragma unroll
      for (int mt = 0; mt < 2; mt++) {
        int r = wm * 32 + mt * 16 + g4;
        af[mt][0] = __float_as_uint(As[r][ks + tq]);
        af[mt][1] = __float_as_uint(As[r + 8][ks + tq]);
        af[mt][2] = __float_as_uint(As[r][ks + tq + 4]);
        af[mt][3] = __float_as_uint(As[r + 8][ks + tq + 4]);
      }
      #pragma unroll
      for (int nt = 0; nt < 4; nt++) {
        int ccol = wn * 32 + nt * 8 + g4;
        uint32_t b0 = __float_as_uint(Bs[ks + tq][ccol]);
        uint32_t b1 = __float_as_uint(Bs[ks + tq + 4][ccol]);
        #pragma unroll
        for (int mt = 0; mt < 2; mt++)
          mma8(acc[mt][nt], af[mt][0], af[mt][1], af[mt][2], af[mt][3], b0, b1);
      }
    }
    __syncthreads();
  }
  size_t gb = (size_t)(dg * T_ + t) * (N_ * B_);
  #pragma unroll
  for (int mt = 0; mt < 2; mt++) {
    int brow = wm * 32 + mt * 16 + g4;
    #pragma unroll
    for (int nt = 0; nt < 4; nt++) {
      int nc = n0 + wn * 32 + nt * 8 + 2 * tq;
      *(float2*)&g_G[gb + (size_t)brow * N_ + nc] =
          make_float2(acc[mt][nt][0], acc[mt][nt][1]);
      *(float2*)&g_G[gb + (size_t)(brow + 8) * N_ + nc] =
          make_float2(acc[mt][nt][2], acc[mt][nt][3]);
    }
  }
}

// ---------------- Phase 2: persistent recurrent kernel ---------------------
// 512 thr. Warp PAIR kq (warps 2kq, 2kq+1) owns k-slice [kq*128, kq*128+128),
// staged privately in 2x(64b x 40) smem ring with named-barrier sync.
// Warp rg in pair handles gates 2rg, 2rg+1. U software-pipelined in regs.
#define BUFW 2560                  // 64 * 40 words per chunk buffer
#define PAIRW 5120                 // 2 buffers
#define SMEM_BYTES (8 * PAIRW * 4) // 163840
// zs overlaid on each pair's OWN staging region: [r 64][cl 66] (4224 < 5120)
#define ZS(q, r, cl) ((q) * PAIRW + (r) * 66 + (cl))

__global__ void __launch_bounds__(512) k_recur(PU pu, float* __restrict__ out) {
  extern __shared__ float sm[];
  uint32_t smb = (uint32_t)__cvta_generic_to_shared(sm);
  int tid = threadIdx.x, wid = tid >> 5, lane = tid & 31;
  int g4 = lane >> 2, tq = lane & 3;
  int dir = blockIdx.x >> 6, tile = blockIdx.x & 63, rn = tile << 4;
  int rg = wid & 1, kq = wid >> 1;
  int pt = rg * 32 + lane;                 // pair-local tid 0..63
  int barid = 1 + kq;

  const uint4* upk = g_Upk + (((size_t)dir * 64 + tile) << 14)
                     + kq * 2048 + 2 * rg * 32 + lane;
  uint32_t pair_smb = smb + kq * PAIRW * 4;

  // elementwise ownership: b = tid>>3, n = rn + nn, nn+1
  int b_e = tid >> 3;
  int nn = (tid & 7) << 1;

  float bia[4][2];
  #pragma unroll
  for (int g = 0; g < 4; g++) {
    bia[g][0] = pu.bia[dir * 4 + g][rn + nn];
    bia[g][1] = pu.bia[dir * 4 + g][rn + nn + 1];
  }
  const float* Gb0 = g_G + (size_t)(dir * 3 + 0) * T_ * N_ * B_;
  const float* Gb1 = g_G + (size_t)(dir * 3 + 1) * T_ * N_ * B_;
  const float* Gb2 = g_G + (size_t)(dir * 3 + 2) * T_ * N_ * B_;
  int hslot0 = kperm(rn + nn), hslot1 = kperm(rn + nn + 1);
  unsigned* barp = &g_bar[dir * T_];

  float creg[2] = {0.f, 0.f};

  // U pipeline: A0/A1 always hold the uint4s for the upcoming k-step.
  uint4 A0 = __ldg(upk), A1 = __ldg(upk + 32);

  for (int s = 0; s < T_; ++s) {
    const float* hsrc = g_hP[s & 1][dir];
    const float* hkq = hsrc + kq * 128;

    // stage chunks 0,1 into bufs 0,1 (pair-private)
    #pragma unroll
    for (int c0 = 0; c0 < 2; c0++) {
      #pragma unroll
      for (int j = 0; j < 8; j++) {
        int unit = pt + j * 64;
        int b = unit >> 3, seg = unit & 7;
        cpa16(pair_smb + (c0 * BUFW + b * 40 + seg * 4) * 4,
              hkq + b * N_ + c0 * 32 + seg * 4);
      }
      asm volatile("cp.async.commit_group;");
    }

    // prefetch this step's G (coalesced float2, [t][b][n] layout)
    size_t goff = ((size_t)s * B_ + b_e) * N_ + rn + nn;
    float2 gq0 = __ldg((const float2*)(Gb0 + goff));
    float2 gq1 = __ldg((const float2*)(Gb1 + goff));
    float2 gq2 = __ldg((const float2*)(Gb2 + goff));

    float acc[2][8][4];
    #pragma unroll
    for (int m = 0; m < 2; m++)
      #pragma unroll
      for (int nt = 0; nt < 8; nt++)
        #pragma unroll
        for (int cc = 0; cc < 4; cc++) acc[m][nt][cc] = 0.f;

    // flattened 16 k-steps (4 chunks x 4), U pipelined one k-step ahead
    #pragma unroll
    for (int t = 0; t < 16; ++t) {
      int c = t >> 2;
      if ((t & 3) == 0) {
        if (c < 3) asm volatile("cp.async.wait_group 1;");
        else       asm volatile("cp.async.wait_group 0;");
        barp64(barid);                   // chunk c visible to both warps
      }
      int tn = (t + 1) & 15;             // t=15 wraps to next step's t=0
      const uint4* upn = upk + ((tn >> 2) * 512 + (tn & 3) * 128);
      uint4 An0 = __ldg(upn), An1 = __ldg(upn + 32);

      const float* bb = sm + kq * PAIRW + ((t >> 2) & 1) * BUFW
                        + (t & 3) * 8 + 2 * tq;
      #pragma unroll
      for (int nt = 0; nt < 8; ++nt) {
        uint2 Bv = *(const uint2*)(bb + (nt * 8 + g4) * 40);
        mma8(acc[0][nt], A0.x, A0.y, A0.z, A0.w, Bv.x, Bv.y);
        mma8(acc[1][nt], A1.x, A1.y, A1.z, A1.w, Bv.x, Bv.y);
      }
      A0 = An0; A1 = An1;

      if ((t & 3) == 3 && c < 2) {
        barp64(barid);                   // both warps done with buf c&1
        int cn = c + 2;
        #pragma unroll
        for (int j = 0; j < 8; j++) {
          int unit = pt + j * 64;
          int b = unit >> 3, seg = unit & 7;
          cpa16(pair_smb + ((c & 1) * BUFW + b * 40 + seg * 4) * 4,
                hkq + b * N_ + cn * 32 + seg * 4);
        }
        asm volatile("cp.async.commit_group;");
      }
    }

    barp64(barid);   // partner done with buf1 -> pair region reusable as zs

    // write k-partials into OWN pair region: zs[kq][gate*16+n][b]
    #pragma unroll
    for (int m = 0; m < 2; m++) {
      int gate = 2 * rg + m;
      #pragma unroll
      for (int nt = 0; nt < 8; nt++) {
        int cl = nt * 8 + 2 * tq;
        *(float2*)&sm[ZS(kq, gate * 16 + g4, cl)] =
            make_float2(acc[m][nt][0], acc[m][nt][1]);
        *(float2*)&sm[ZS(kq, gate * 16 + g4 + 8, cl)] =
            make_float2(acc[m][nt][2], acc[m][nt][3]);
      }
    }
    __syncthreads();

    // elementwise LSTM cell (2 consecutive n per thread, one b)
    float z[4][2];
    #pragma unroll
    for (int g = 0; g < 4; g++) {
      #pragma unroll
      for (int e = 0; e < 2; e++) {
        float zz = bia[g][e];
        #pragma unroll
        for (int q = 0; q < 8; q++) zz += sm[ZS(q, g * 16 + nn + e, b_e)];
        z[g][e] = zz;
      }
    }
    float* hdst = g_hP[(s + 1) & 1][dir];
    int t_out = dir ? (T_ - 1 - s) : s;
    float2 ho;
    #pragma unroll
    for (int e = 0; e < 2; e++) {
      float gf = e ? gq0.y : gq0.x;
      float gi = e ? gq1.y : gq1.x;
      float gc = e ? gq2.y : gq2.x;
      float zf = z[0][e] + gf, zi = z[1][e] + gi;
      float zc = z[2][e] + gc, zo = z[3][e] + gf;   // o reuses gf (ref bug)
      float f  = sigm_f(zf);
      float ig = sigm_f(zi);
      float o  = sigm_f(zo);
      float cn = f * creg[e] + ig * tanh_f(zc);
      creg[e] = cn;
      float h = o * tanh_f(cn);
      ((float*)&ho)[e] = h;
      __stcg(hdst + b_e * N_ + (e ? hslot1 : hslot0), __uint_as_float(f2tf(h)));
    }
    *(float2*)(out + ((size_t)t_out * B_ + b_e) * (2 * N_) +
               (size_t)dir * N_ + rn + nn) = ho;

    // per-direction grid barrier: release-acquire via tid0 (no per-thread fence)
    if (s < T_ - 1) {
      __syncthreads();     // all h-stores happen-before tid0's release-atomic
      if (tid == 0) {
        unsigned v;
        asm volatile("atom.add.acq_rel.gpu.global.u32 %0, [%1], 1;"
                     : "=r"(v) : "l"(&barp[s]) : "memory");
        if (v + 1u < NBD) {
          unsigned w;
          do {
            asm volatile("ld.acquire.gpu.global.u32 %0, [%1];"
                         : "=r"(w) : "l"(&barp[s]) : "memory");
            if (w >= NBD) break;
            __nanosleep(32);
          } while (true);
        }
      }
      __syncthreads();     // acquire ordering propagates block-wide
    }
  }
}

extern "C" void kernel_launch(void* const* d_in, const int* in_sizes, int n_in,
                              void* d_out, int out_size) {
  const float* x      = (const float*)d_in[0];
  const float* hidden = (const float*)d_in[1];
  PW pw;
  pw.p[0] = (const float*)d_in[2];   // Wf1
  pw.p[1] = (const float*)d_in[3];   // Wi1
  pw.p[2] = (const float*)d_in[4];   // Wc1
  pw.p[3] = (const float*)d_in[13];  // Wf2
  pw.p[4] = (const float*)d_in[14];  // Wi2
  pw.p[5] = (const float*)d_in[15];  // Wc2

  PU pu;  // gate order f,i,c,o
  pu.U[0] = (const float*)d_in[5];   // Uf1
  pu.U[1] = (const float*)d_in[6];   // Ui1
  pu.U[2] = (const float*)d_in[8];   // Uc1
  pu.U[3] = (const float*)d_in[7];   // Uo1
  pu.U[4] = (const float*)d_in[16];  // Uf2
  pu.U[5] = (const float*)d_in[17];  // Ui2
  pu.U[6] = (const float*)d_in[19];  // Uc2
  pu.U[7] = (const float*)d_in[18];  // Uo2
  pu.bia[0] = (const float*)d_in[9];   // bf1
  pu.bia[1] = (const float*)d_in[10];  // bi1
  pu.bia[2] = (const float*)d_in[12];  // bc1
  pu.bia[3] = (const float*)d_in[11];  // bo1
  pu.bia[4] = (const float*)d_in[20];  // bf2
  pu.bia[5] = (const float*)d_in[21];  // bi2
  pu.bia[6] = (const float*)d_in[23];  // bc2
  pu.bia[7] = (const float*)d_in[22];  // bo2

  static int smem_set = 0;
  if (!smem_set) {
    cudaFuncSetAttribute(k_recur, cudaFuncAttributeMaxDynamicSharedMemorySize,
                         SMEM_BYTES);
    smem_set = 1;
  }

  k_init<<<256, 256>>>(hidden);
  k_pack<<<8192, 256>>>(pu);
  k_gemm_xw<<<dim3(8, 256, 6), 256>>>(x, pw);
  k_recur<<<NB_REC, 512, SMEM_BYTES>>>(pu, (float*)d_out);
}